// round 1
// baseline (speedup 1.0000x reference)
#include <cuda_runtime.h>
#include <cuda_bf16.h>
#include <mma.h>
#include <math.h>

using namespace nvcuda;

#define B_  2
#define T_  2048
#define C_  1024
#define H_  16
#define D_  64
#define M_  (B_ * T_)   // 4096 rows

// ---------------- scratch (device globals: no allocation allowed) ----------
__device__ __align__(128) float g_q[(size_t)M_ * C_];
__device__ __align__(128) float g_k[(size_t)M_ * C_];
__device__ __align__(128) float g_v[(size_t)M_ * C_];
__device__ __align__(128) float g_o[(size_t)M_ * C_];

// ---------------------------------------------------------------------------
// GEMM: Y[M,N] = A[M,K] @ B[N,K]^T   (both operands K-contiguous, row-major)
// tf32 wmma, 64x64 block tile, K-chunks of 32, 4 warps (each warp 16x64).
// ---------------------------------------------------------------------------
#define GST 40   // shared stride (multiple of 8, 160B rows -> 16B aligned)

__global__ __launch_bounds__(128) void gemm_tn(
    const float* __restrict__ A, const float* __restrict__ Bm,
    float* __restrict__ Y, int M, int N, int K)
{
    __shared__ float As[64 * GST];
    __shared__ float Bs[64 * GST];

    const int m0 = blockIdx.y * 64;
    const int n0 = blockIdx.x * 64;
    const int w  = threadIdx.x >> 5;

    wmma::fragment<wmma::accumulator, 16, 16, 8, float> acc[4];
#pragma unroll
    for (int i = 0; i < 4; i++) wmma::fill_fragment(acc[i], 0.0f);

    for (int kc = 0; kc < K; kc += 32) {
#pragma unroll
        for (int i = threadIdx.x; i < 512; i += 128) {
            int r = i >> 3;
            int c = (i & 7) << 2;
            *(float4*)&As[r * GST + c] =
                *(const float4*)&A[(size_t)(m0 + r) * K + kc + c];
            *(float4*)&Bs[r * GST + c] =
                *(const float4*)&Bm[(size_t)(n0 + r) * K + kc + c];
        }
        __syncthreads();

#pragma unroll
        for (int k8 = 0; k8 < 4; k8++) {
            wmma::fragment<wmma::matrix_a, 16, 16, 8, wmma::precision::tf32,
                           wmma::row_major> a;
            wmma::load_matrix_sync(a, &As[w * 16 * GST + k8 * 8], GST);
#pragma unroll
            for (int i = 0; i < a.num_elements; i++)
                a.x[i] = wmma::__float_to_tf32(a.x[i]);
#pragma unroll
            for (int nt = 0; nt < 4; nt++) {
                wmma::fragment<wmma::matrix_b, 16, 16, 8, wmma::precision::tf32,
                               wmma::col_major> b;
                wmma::load_matrix_sync(b, &Bs[nt * 16 * GST + k8 * 8], GST);
#pragma unroll
                for (int i = 0; i < b.num_elements; i++)
                    b.x[i] = wmma::__float_to_tf32(b.x[i]);
                wmma::mma_sync(acc[nt], a, b, acc[nt]);
            }
        }
        __syncthreads();
    }

#pragma unroll
    for (int nt = 0; nt < 4; nt++)
        wmma::store_matrix_sync(&Y[(size_t)(m0 + w * 16) * N + n0 + nt * 16],
                                acc[nt], N, wmma::mem_row_major);
}

// ---------------------------------------------------------------------------
// RoPE, applied in-place pairwise on (2j, 2j+1) within each head.
// Equivalent to the reference's concat layout under Q·K^T invariance.
// ---------------------------------------------------------------------------
__global__ __launch_bounds__(256) void rope_kernel(float* __restrict__ q,
                                                   float* __restrict__ k)
{
    int idx = blockIdx.x * blockDim.x + threadIdx.x;
    const int total = M_ * (C_ / 2);
    if (idx >= total) return;

    int row  = idx >> 9;          // / (C_/2) = 512
    int col2 = idx & 511;
    int t    = row & (T_ - 1);
    int j    = col2 & 31;         // pair index within head (D/2 = 32)
    int head = col2 >> 5;

    size_t base = (size_t)row * C_ + head * D_ + 2 * j;

    double inv = exp(-((double)(2 * j) / 64.0) * log(10000.0));
    double ang = (double)t * inv;
    float  c   = (float)cos(ang);
    float  s   = (float)sin(ang);

    float* buf = (blockIdx.y == 0) ? q : k;
    float x0 = buf[base];
    float x1 = buf[base + 1];
    buf[base]     = x0 * c - x1 * s;
    buf[base + 1] = x0 * s + x1 * c;
}

// ---------------------------------------------------------------------------
// Flash attention (causal). BM = BN = 64, D = 64, 4 warps.
// S = Q K^T and O += P V via tf32 wmma; online softmax in shared memory.
// ---------------------------------------------------------------------------
#define FST 72   // shared stride for all 64-wide tiles

__global__ __launch_bounds__(128) void flash_kernel(
    const float* __restrict__ q, const float* __restrict__ k,
    const float* __restrict__ v, float* __restrict__ o)
{
    extern __shared__ float sm[];
    float* Qs = sm;                 // 64*FST
    float* Ks = Qs + 64 * FST;
    float* Vs = Ks + 64 * FST;
    float* Ss = Vs + 64 * FST;      // scores -> probs
    float* Os = Ss + 64 * FST;      // output accumulator
    float* Pt = Os + 64 * FST;      // PV partial tile

    __shared__ float m_sh[64], l_sh[64], a_sh[64];

    const int bh  = blockIdx.y;
    const int b   = bh >> 4;        // / H_
    const int h   = bh & 15;
    const int q0  = blockIdx.x * 64;
    const int tid = threadIdx.x;
    const int w   = tid >> 5;
    const float scale = 0.125f;     // 1/sqrt(D)

    const size_t qrow = (size_t)(b * T_ + q0) * C_ + h * D_;

    // load Q tile
    for (int i = tid; i < 1024; i += 128) {
        int r = i >> 4, c = (i & 15) << 2;
        *(float4*)&Qs[r * FST + c] =
            *(const float4*)&q[qrow + (size_t)r * C_ + c];
    }
    for (int i = tid; i < 4096; i += 128) {
        int r = i >> 6, c = i & 63;
        Os[r * FST + c] = 0.0f;
    }
    if (tid < 64) { m_sh[tid] = -INFINITY; l_sh[tid] = 0.0f; }
    __syncthreads();

    for (int n0 = 0; n0 <= q0; n0 += 64) {
        const size_t krow = (size_t)(b * T_ + n0) * C_ + h * D_;
        for (int i = tid; i < 1024; i += 128) {
            int r = i >> 4, c = (i & 15) << 2;
            *(float4*)&Ks[r * FST + c] =
                *(const float4*)&k[krow + (size_t)r * C_ + c];
            *(float4*)&Vs[r * FST + c] =
                *(const float4*)&v[krow + (size_t)r * C_ + c];
        }
        __syncthreads();

        // ---- S = Q K^T (16x64 strip per warp) ----
        {
            wmma::fragment<wmma::accumulator, 16, 16, 8, float> sacc[4];
#pragma unroll
            for (int i = 0; i < 4; i++) wmma::fill_fragment(sacc[i], 0.0f);
#pragma unroll
            for (int k8 = 0; k8 < 8; k8++) {
                wmma::fragment<wmma::matrix_a, 16, 16, 8,
                               wmma::precision::tf32, wmma::row_major> a;
                wmma::load_matrix_sync(a, &Qs[w * 16 * FST + k8 * 8], FST);
#pragma unroll
                for (int i = 0; i < a.num_elements; i++)
                    a.x[i] = wmma::__float_to_tf32(a.x[i]);
#pragma unroll
                for (int nt = 0; nt < 4; nt++) {
                    wmma::fragment<wmma::matrix_b, 16, 16, 8,
                                   wmma::precision::tf32, wmma::col_major> bb;
                    wmma::load_matrix_sync(bb, &Ks[nt * 16 * FST + k8 * 8], FST);
#pragma unroll
                    for (int i = 0; i < bb.num_elements; i++)
                        bb.x[i] = wmma::__float_to_tf32(bb.x[i]);
                    wmma::mma_sync(sacc[nt], a, bb, sacc[nt]);
                }
            }
#pragma unroll
            for (int nt = 0; nt < 4; nt++)
                wmma::store_matrix_sync(&Ss[w * 16 * FST + nt * 16], sacc[nt],
                                        FST, wmma::mem_row_major);
        }
        __syncthreads();

        // ---- online softmax (one thread per row) ----
        if (tid < 64) {
            const int r    = tid;
            const int cmax = (n0 == q0) ? r : 63;   // causal mask only on diagonal
            float mo = m_sh[r];
            float mx = mo;
            for (int c = 0; c <= cmax; c++)
                mx = fmaxf(mx, Ss[r * FST + c] * scale);
            float alpha = __expf(mo - mx);
            float sum = 0.0f;
            for (int c = 0; c < 64; c++) {
                float p = (c <= cmax) ? __expf(Ss[r * FST + c] * scale - mx)
                                      : 0.0f;
                Ss[r * FST + c] = p;
                sum += p;
            }
            l_sh[r] = l_sh[r] * alpha + sum;
            m_sh[r] = mx;
            a_sh[r] = alpha;
        }
        __syncthreads();

        // ---- PV (16x64 strip per warp) ----
        {
            wmma::fragment<wmma::accumulator, 16, 16, 8, float> oacc[4];
#pragma unroll
            for (int i = 0; i < 4; i++) wmma::fill_fragment(oacc[i], 0.0f);
#pragma unroll
            for (int k8 = 0; k8 < 8; k8++) {
                wmma::fragment<wmma::matrix_a, 16, 16, 8,
                               wmma::precision::tf32, wmma::row_major> a;
                wmma::load_matrix_sync(a, &Ss[w * 16 * FST + k8 * 8], FST);
#pragma unroll
                for (int i = 0; i < a.num_elements; i++)
                    a.x[i] = wmma::__float_to_tf32(a.x[i]);
#pragma unroll
                for (int dt = 0; dt < 4; dt++) {
                    wmma::fragment<wmma::matrix_b, 16, 16, 8,
                                   wmma::precision::tf32, wmma::row_major> bb;
                    wmma::load_matrix_sync(bb, &Vs[k8 * 8 * FST + dt * 16], FST);
#pragma unroll
                    for (int i = 0; i < bb.num_elements; i++)
                        bb.x[i] = wmma::__float_to_tf32(bb.x[i]);
                    wmma::mma_sync(oacc[dt], a, bb, oacc[dt]);
                }
            }
#pragma unroll
            for (int dt = 0; dt < 4; dt++)
                wmma::store_matrix_sync(&Pt[w * 16 * FST + dt * 16], oacc[dt],
                                        FST, wmma::mem_row_major);
        }
        __syncthreads();

        // ---- merge: O = O*alpha + PV ----
        for (int i = tid; i < 4096; i += 128) {
            int r = i >> 6, c = i & 63;
            Os[r * FST + c] = Os[r * FST + c] * a_sh[r] + Pt[r * FST + c];
        }
        __syncthreads();
    }

    // ---- normalize + write ----
    for (int i = tid; i < 4096; i += 128) {
        int r = i >> 6, c = i & 63;
        o[qrow + (size_t)r * C_ + c] = Os[r * FST + c] / l_sh[r];
    }
}

// ---------------------------------------------------------------------------
extern "C" void kernel_launch(void* const* d_in, const int* in_sizes, int n_in,
                              void* d_out, int out_size)
{
    (void)in_sizes; (void)n_in; (void)out_size;
    const float* x  = (const float*)d_in[0];
    const float* Wq = (const float*)d_in[1];
    const float* Wk = (const float*)d_in[2];
    const float* Wv = (const float*)d_in[3];
    const float* Wo = (const float*)d_in[4];
    float* out = (float*)d_out;

    float *q, *k, *v, *ob;
    cudaGetSymbolAddress((void**)&q,  g_q);
    cudaGetSymbolAddress((void**)&k,  g_k);
    cudaGetSymbolAddress((void**)&v,  g_v);
    cudaGetSymbolAddress((void**)&ob, g_o);

    const dim3 gg(C_ / 64, M_ / 64);   // (16, 64)

    gemm_tn<<<gg, 128>>>(x, Wq, q, M_, C_, C_);
    gemm_tn<<<gg, 128>>>(x, Wk, k, M_, C_, C_);
    gemm_tn<<<gg, 128>>>(x, Wv, v, M_, C_, C_);

    const int pairs = M_ * (C_ / 2);
    rope_kernel<<<dim3((pairs + 255) / 256, 2), 256>>>(q, k);

    const int fsmem = 6 * 64 * FST * (int)sizeof(float);   // 110,592 B
    cudaFuncSetAttribute(flash_kernel,
                         cudaFuncAttributeMaxDynamicSharedMemorySize, fsmem);
    flash_kernel<<<dim3(T_ / 64, B_ * H_), 128, fsmem>>>(q, k, v, ob);

    gemm_tn<<<gg, 128>>>(ob, Wo, out, M_, C_, C_);
}

// round 2
// speedup vs baseline: 1.5726x; 1.5726x over previous
#include <cuda_runtime.h>
#include <cuda_bf16.h>
#include <mma.h>
#include <math.h>

using namespace nvcuda;

#define B_  2
#define T_  2048
#define C_  1024
#define H_  16
#define D_  64
#define M_  (B_ * T_)   // 4096 rows

// ---------------- scratch (device globals: no allocation allowed) ----------
__device__ __align__(128) float g_q[(size_t)M_ * C_];
__device__ __align__(128) float g_k[(size_t)M_ * C_];
__device__ __align__(128) float g_v[(size_t)M_ * C_];
__device__ __align__(128) float g_o[(size_t)M_ * C_];
__device__ __align__(128) float2 g_rope_tab[T_ * 32];   // (cos, sin) per (t, j)

// ---------------------------------------------------------------------------
// GEMM: Y[M,N] = A[M,K] @ B[N,K]^T   (both operands K-contiguous, row-major)
// tf32 wmma, 128x64 block tile, K-chunks of 32, 8 warps (each warp 32x32).
// ---------------------------------------------------------------------------
#define GST 40   // shared stride (multiple of 8)

__global__ __launch_bounds__(256) void gemm_tn(
    const float* __restrict__ A, const float* __restrict__ Bm,
    float* __restrict__ Y, int M, int N, int K)
{
    __shared__ float As[128 * GST];
    __shared__ float Bs[64 * GST];

    const int m0 = blockIdx.y * 128;
    const int n0 = blockIdx.x * 64;
    const int w  = threadIdx.x >> 5;
    const int wm = w & 3;        // 0..3 -> 32-row strip
    const int wn = w >> 2;       // 0..1 -> 32-col strip

    wmma::fragment<wmma::accumulator, 16, 16, 8, float> acc[2][2];
#pragma unroll
    for (int i = 0; i < 2; i++)
#pragma unroll
        for (int j = 0; j < 2; j++) wmma::fill_fragment(acc[i][j], 0.0f);

    for (int kc = 0; kc < K; kc += 32) {
#pragma unroll
        for (int i = threadIdx.x; i < 1024; i += 256) {
            int r = i >> 3;
            int c = (i & 7) << 2;
            *(float4*)&As[r * GST + c] =
                *(const float4*)&A[(size_t)(m0 + r) * K + kc + c];
        }
#pragma unroll
        for (int i = threadIdx.x; i < 512; i += 256) {
            int r = i >> 3;
            int c = (i & 7) << 2;
            *(float4*)&Bs[r * GST + c] =
                *(const float4*)&Bm[(size_t)(n0 + r) * K + kc + c];
        }
        __syncthreads();

#pragma unroll
        for (int k8 = 0; k8 < 4; k8++) {
            wmma::fragment<wmma::matrix_a, 16, 16, 8, wmma::precision::tf32,
                           wmma::row_major> a[2];
            wmma::fragment<wmma::matrix_b, 16, 16, 8, wmma::precision::tf32,
                           wmma::col_major> b[2];
#pragma unroll
            for (int i = 0; i < 2; i++) {
                wmma::load_matrix_sync(a[i],
                    &As[(wm * 32 + i * 16) * GST + k8 * 8], GST);
#pragma unroll
                for (int e = 0; e < a[i].num_elements; e++)
                    a[i].x[e] = wmma::__float_to_tf32(a[i].x[e]);
            }
#pragma unroll
            for (int j = 0; j < 2; j++) {
                wmma::load_matrix_sync(b[j],
                    &Bs[(wn * 32 + j * 16) * GST + k8 * 8], GST);
#pragma unroll
                for (int e = 0; e < b[j].num_elements; e++)
                    b[j].x[e] = wmma::__float_to_tf32(b[j].x[e]);
            }
#pragma unroll
            for (int i = 0; i < 2; i++)
#pragma unroll
                for (int j = 0; j < 2; j++)
                    wmma::mma_sync(acc[i][j], a[i], b[j], acc[i][j]);
        }
        __syncthreads();
    }

#pragma unroll
    for (int i = 0; i < 2; i++)
#pragma unroll
        for (int j = 0; j < 2; j++)
            wmma::store_matrix_sync(
                &Y[(size_t)(m0 + wm * 32 + i * 16) * N + n0 + wn * 32 + j * 16],
                acc[i][j], N, wmma::mem_row_major);
}

// ---------------------------------------------------------------------------
// RoPE: precompute (cos, sin) table once (double precision, tiny),
// then a memory-bound apply pass rotating q and k in place.
// ---------------------------------------------------------------------------
__global__ __launch_bounds__(256) void rope_table_kernel(float2* __restrict__ tab)
{
    int idx = blockIdx.x * blockDim.x + threadIdx.x;   // t*32 + j
    if (idx >= T_ * 32) return;
    int t = idx >> 5;
    int j = idx & 31;
    double inv = exp(-((double)(2 * j) / 64.0) * log(10000.0));
    double ang = (double)t * inv;
    tab[idx] = make_float2((float)cos(ang), (float)sin(ang));
}

__global__ __launch_bounds__(256) void rope_apply_kernel(
    float* __restrict__ q, float* __restrict__ k,
    const float2* __restrict__ tab)
{
    int idx = blockIdx.x * blockDim.x + threadIdx.x;
    const int total = M_ * (C_ / 2);
    if (idx >= total) return;

    int row  = idx >> 9;          // / 512
    int col2 = idx & 511;
    int t    = row & (T_ - 1);
    int j    = col2 & 31;
    int head = col2 >> 5;

    float2 cs = tab[t * 32 + j];
    size_t base = (size_t)row * C_ + head * D_ + 2 * j;

    float2 qv = *(float2*)&q[base];
    float2 kv = *(float2*)&k[base];
    *(float2*)&q[base] = make_float2(qv.x * cs.x - qv.y * cs.y,
                                     qv.x * cs.y + qv.y * cs.x);
    *(float2*)&k[base] = make_float2(kv.x * cs.x - kv.y * cs.y,
                                     kv.x * cs.y + kv.y * cs.x);
}

// ---------------------------------------------------------------------------
// Flash attention (causal). BM = BN = 64, D = 64, 4 warps.
// ---------------------------------------------------------------------------
#define FST 72

__global__ __launch_bounds__(128) void flash_kernel(
    const float* __restrict__ q, const float* __restrict__ k,
    const float* __restrict__ v, float* __restrict__ o)
{
    extern __shared__ float sm[];
    float* Qs = sm;
    float* Ks = Qs + 64 * FST;
    float* Vs = Ks + 64 * FST;
    float* Ss = Vs + 64 * FST;
    float* Os = Ss + 64 * FST;
    float* Pt = Os + 64 * FST;

    __shared__ float m_sh[64], l_sh[64], a_sh[64];

    const int bh  = blockIdx.y;
    const int b   = bh >> 4;
    const int h   = bh & 15;
    const int q0  = blockIdx.x * 64;
    const int tid = threadIdx.x;
    const int w   = tid >> 5;
    const float scale = 0.125f;

    const size_t qrow = (size_t)(b * T_ + q0) * C_ + h * D_;

    for (int i = tid; i < 1024; i += 128) {
        int r = i >> 4, c = (i & 15) << 2;
        *(float4*)&Qs[r * FST + c] =
            *(const float4*)&q[qrow + (size_t)r * C_ + c];
    }
    for (int i = tid; i < 4096; i += 128) {
        int r = i >> 6, c = i & 63;
        Os[r * FST + c] = 0.0f;
    }
    if (tid < 64) { m_sh[tid] = -INFINITY; l_sh[tid] = 0.0f; }
    __syncthreads();

    for (int n0 = 0; n0 <= q0; n0 += 64) {
        const size_t krow = (size_t)(b * T_ + n0) * C_ + h * D_;
        for (int i = tid; i < 1024; i += 128) {
            int r = i >> 4, c = (i & 15) << 2;
            *(float4*)&Ks[r * FST + c] =
                *(const float4*)&k[krow + (size_t)r * C_ + c];
            *(float4*)&Vs[r * FST + c] =
                *(const float4*)&v[krow + (size_t)r * C_ + c];
        }
        __syncthreads();

        {
            wmma::fragment<wmma::accumulator, 16, 16, 8, float> sacc[4];
#pragma unroll
            for (int i = 0; i < 4; i++) wmma::fill_fragment(sacc[i], 0.0f);
#pragma unroll
            for (int k8 = 0; k8 < 8; k8++) {
                wmma::fragment<wmma::matrix_a, 16, 16, 8,
                               wmma::precision::tf32, wmma::row_major> a;
                wmma::load_matrix_sync(a, &Qs[w * 16 * FST + k8 * 8], FST);
#pragma unroll
                for (int i = 0; i < a.num_elements; i++)
                    a.x[i] = wmma::__float_to_tf32(a.x[i]);
#pragma unroll
                for (int nt = 0; nt < 4; nt++) {
                    wmma::fragment<wmma::matrix_b, 16, 16, 8,
                                   wmma::precision::tf32, wmma::col_major> bb;
                    wmma::load_matrix_sync(bb, &Ks[nt * 16 * FST + k8 * 8], FST);
#pragma unroll
                    for (int i = 0; i < bb.num_elements; i++)
                        bb.x[i] = wmma::__float_to_tf32(bb.x[i]);
                    wmma::mma_sync(sacc[nt], a, bb, sacc[nt]);
                }
            }
#pragma unroll
            for (int nt = 0; nt < 4; nt++)
                wmma::store_matrix_sync(&Ss[w * 16 * FST + nt * 16], sacc[nt],
                                        FST, wmma::mem_row_major);
        }
        __syncthreads();

        if (tid < 64) {
            const int r    = tid;
            const int cmax = (n0 == q0) ? r : 63;
            float mo = m_sh[r];
            float mx = mo;
            for (int c = 0; c <= cmax; c++)
                mx = fmaxf(mx, Ss[r * FST + c] * scale);
            float alpha = __expf(mo - mx);
            float sum = 0.0f;
            for (int c = 0; c < 64; c++) {
                float p = (c <= cmax) ? __expf(Ss[r * FST + c] * scale - mx)
                                      : 0.0f;
                Ss[r * FST + c] = p;
                sum += p;
            }
            l_sh[r] = l_sh[r] * alpha + sum;
            m_sh[r] = mx;
            a_sh[r] = alpha;
        }
        __syncthreads();

        {
            wmma::fragment<wmma::accumulator, 16, 16, 8, float> oacc[4];
#pragma unroll
            for (int i = 0; i < 4; i++) wmma::fill_fragment(oacc[i], 0.0f);
#pragma unroll
            for (int k8 = 0; k8 < 8; k8++) {
                wmma::fragment<wmma::matrix_a, 16, 16, 8,
                               wmma::precision::tf32, wmma::row_major> a;
                wmma::load_matrix_sync(a, &Ss[w * 16 * FST + k8 * 8], FST);
#pragma unroll
                for (int i = 0; i < a.num_elements; i++)
                    a.x[i] = wmma::__float_to_tf32(a.x[i]);
#pragma unroll
                for (int dt = 0; dt < 4; dt++) {
                    wmma::fragment<wmma::matrix_b, 16, 16, 8,
                                   wmma::precision::tf32, wmma::row_major> bb;
                    wmma::load_matrix_sync(bb, &Vs[k8 * 8 * FST + dt * 16], FST);
#pragma unroll
                    for (int i = 0; i < bb.num_elements; i++)
                        bb.x[i] = wmma::__float_to_tf32(bb.x[i]);
                    wmma::mma_sync(oacc[dt], a, bb, oacc[dt]);
                }
            }
#pragma unroll
            for (int dt = 0; dt < 4; dt++)
                wmma::store_matrix_sync(&Pt[w * 16 * FST + dt * 16], oacc[dt],
                                        FST, wmma::mem_row_major);
        }
        __syncthreads();

        for (int i = tid; i < 4096; i += 128) {
            int r = i >> 6, c = i & 63;
            Os[r * FST + c] = Os[r * FST + c] * a_sh[r] + Pt[r * FST + c];
        }
        __syncthreads();
    }

    for (int i = tid; i < 4096; i += 128) {
        int r = i >> 6, c = i & 63;
        o[qrow + (size_t)r * C_ + c] = Os[r * FST + c] / l_sh[r];
    }
}

// ---------------------------------------------------------------------------
extern "C" void kernel_launch(void* const* d_in, const int* in_sizes, int n_in,
                              void* d_out, int out_size)
{
    (void)in_sizes; (void)n_in; (void)out_size;
    const float* x  = (const float*)d_in[0];
    const float* Wq = (const float*)d_in[1];
    const float* Wk = (const float*)d_in[2];
    const float* Wv = (const float*)d_in[3];
    const float* Wo = (const float*)d_in[4];
    float* out = (float*)d_out;

    float *q, *k, *v, *ob;
    float2* tab;
    cudaGetSymbolAddress((void**)&q,   g_q);
    cudaGetSymbolAddress((void**)&k,   g_k);
    cudaGetSymbolAddress((void**)&v,   g_v);
    cudaGetSymbolAddress((void**)&ob,  g_o);
    cudaGetSymbolAddress((void**)&tab, g_rope_tab);

    const dim3 gg(C_ / 64, M_ / 128);   // (16, 32)

    rope_table_kernel<<<(T_ * 32 + 255) / 256, 256>>>(tab);

    gemm_tn<<<gg, 256>>>(x, Wq, q, M_, C_, C_);
    gemm_tn<<<gg, 256>>>(x, Wk, k, M_, C_, C_);
    gemm_tn<<<gg, 256>>>(x, Wv, v, M_, C_, C_);

    const int pairs = M_ * (C_ / 2);
    rope_apply_kernel<<<(pairs + 255) / 256, 256>>>(q, k, tab);

    const int fsmem = 6 * 64 * FST * (int)sizeof(float);
    cudaFuncSetAttribute(flash_kernel,
                         cudaFuncAttributeMaxDynamicSharedMemorySize, fsmem);
    flash_kernel<<<dim3(T_ / 64, B_ * H_), 128, fsmem>>>(q, k, v, ob);

    gemm_tn<<<gg, 256>>>(ob, Wo, out, M_, C_, C_);
}